// round 15
// baseline (speedup 1.0000x reference)
#include <cuda_runtime.h>
#include <cuda_fp16.h>
#include <math.h>
#include <stdint.h>

#define NB   8
#define CDIM 256
#define CKD  64
#define NN   4096

// ---------------------------------------------------------------------------
// Scratch (allocation-free rule: __device__ globals). fp16 pipeline.
// ---------------------------------------------------------------------------
__device__ __half g_xf[NB * CDIM * NN];
__device__ __half g_Qf[NB * CKD  * NN];
__device__ __half g_Kf[NB * CKD  * NN];
__device__ __half g_Vf[NB * CDIM * NN];
__device__ __half g_Of[NB * CDIM * NN];
__device__ __half g_Wqh[CKD * CDIM],  g_Wql[CKD * CDIM];
__device__ __half g_Wkh[CKD * CDIM],  g_Wkl[CKD * CDIM];
__device__ __half g_Wvh[CDIM * CDIM], g_Wvl[CDIM * CDIM];
__device__ __half g_Wgh[CDIM * CDIM], g_Wgl[CDIM * CDIM];

// ---------------------------------------------------------------------------
// Helpers (fragment maps validated R4-R6, fp16 MMA validated R12/R13)
// ---------------------------------------------------------------------------
__device__ __forceinline__ float elu_scaled(float x) {
    const float invN = 1.0f / 4096.0f;
    return (x > 0.f ? x : (expf(x) - 1.f)) * invN;
}
__device__ __forceinline__ void split2h(float x, __half& h, __half& l) {
    h = __float2half(x);
    l = __float2half(x - __half2float(h));
}
__device__ __forceinline__ uint32_t cvta_s(const void* p) {
    return (uint32_t)__cvta_generic_to_shared(p);
}
__device__ __forceinline__ void ldsm_x4(uint32_t* r, uint32_t addr) {
    asm volatile("ldmatrix.sync.aligned.m8n8.x4.shared.b16 {%0,%1,%2,%3},[%4];\n"
                 : "=r"(r[0]), "=r"(r[1]), "=r"(r[2]), "=r"(r[3]) : "r"(addr));
}
__device__ __forceinline__ void ldsm_x4_t(uint32_t* r, uint32_t addr) {
    asm volatile("ldmatrix.sync.aligned.m8n8.x4.trans.shared.b16 {%0,%1,%2,%3},[%4];\n"
                 : "=r"(r[0]), "=r"(r[1]), "=r"(r[2]), "=r"(r[3]) : "r"(addr));
}
__device__ __forceinline__ void mma_fp16(float* c, const uint32_t* a, const uint32_t* b) {
    asm volatile(
        "mma.sync.aligned.m16n8k16.row.col.f32.f16.f16.f32 "
        "{%0,%1,%2,%3},{%4,%5,%6,%7},{%8,%9},{%0,%1,%2,%3};\n"
        : "+f"(c[0]), "+f"(c[1]), "+f"(c[2]), "+f"(c[3])
        : "r"(a[0]), "r"(a[1]), "r"(a[2]), "r"(a[3]), "r"(b[0]), "r"(b[1]));
}
__device__ __forceinline__ void cp16(uint32_t saddr, const void* g) {
    asm volatile("cp.async.cg.shared.global [%0],[%1],16;\n" :: "r"(saddr), "l"(g));
}
__device__ __forceinline__ void cp_commit() {
    asm volatile("cp.async.commit_group;\n" ::: "memory");
}
template <int N> __device__ __forceinline__ void cp_wait() {
    asm volatile("cp.async.wait_group %0;\n" :: "n"(N) : "memory");
}

// ---------------------------------------------------------------------------
// fp32 -> fp16 convert (single) and split (hi/lo).
// ---------------------------------------------------------------------------
__global__ __launch_bounds__(256) void f2h_kernel(
    const float4* __restrict__ in, __half2* __restrict__ o, int n4)
{
    int i = blockIdx.x * blockDim.x + threadIdx.x;
    if (i >= n4) return;
    float4 v = in[i];
    o[i * 2]     = __floats2half2_rn(v.x, v.y);
    o[i * 2 + 1] = __floats2half2_rn(v.z, v.w);
}
__global__ __launch_bounds__(256) void f2h_split_kernel(
    const float4* __restrict__ in, __half2* __restrict__ oh,
    __half2* __restrict__ ol, int n4)
{
    int i = blockIdx.x * blockDim.x + threadIdx.x;
    if (i >= n4) return;
    float4 v = in[i];
    __half h0, l0, h1, l1, h2, l2, h3, l3;
    split2h(v.x, h0, l0); split2h(v.y, h1, l1);
    split2h(v.z, h2, l2); split2h(v.w, h3, l3);
    oh[i * 2]     = __halves2half2(h0, h1);
    oh[i * 2 + 1] = __halves2half2(h2, h3);
    ol[i * 2]     = __halves2half2(l0, l1);
    ol[i * 2 + 1] = __halves2half2(l2, l3);
}

// ---------------------------------------------------------------------------
// fp16 projection (R13-validated, unchanged): Y = W X + bias
// ---------------------------------------------------------------------------
#define WLD 72
#define XLD 136

__global__ __launch_bounds__(256) void proj_fp16_kernel(
    const __half* __restrict__ Wh_g, const __half* __restrict__ Wl_g,
    const float* __restrict__ bias,
    const __half* __restrict__ Xg,
    __half* __restrict__ Yh, float* __restrict__ Yf, int R)
{
    extern __shared__ __half sp[];
    __half* Wh   = sp;
    __half* Wl   = Wh + 64 * WLD;
    __half* Xbuf = Wl + 64 * WLD;

    const int b  = blockIdx.z;
    const int o0 = blockIdx.y * 64;
    const int n0 = blockIdx.x * 128;
    const int tid  = threadIdx.x;
    const int warp = tid >> 5;
    const int lane = tid & 31;

    const __half* Xb = Xg + (size_t)b * CDIM * NN;

    const uint32_t wh_b = cvta_s(Wh), wl_b = cvta_s(Wl);
    const uint32_t x_b  = cvta_s(Xbuf);
    const uint32_t xstride = 64u * XLD * 2;

    auto issueX = [&](int kc, int buf) {
#pragma unroll
        for (int r = 0; r < 4; ++r) {
            int idx = tid + r * 256;
            int row = idx >> 4, c16 = idx & 15;
            uint32_t d = x_b + buf * xstride + (uint32_t)(row * XLD + c16 * 8) * 2;
            cp16(d, Xb + (size_t)(kc * 64 + row) * NN + n0 + c16 * 8);
        }
    };

    const int l7 = lane & 7, rr = lane >> 3;
    const int a_kofs = ((rr & 2) << 2) + l7;
    const int a_mofs = ((rr & 1) << 3);
    const int b_kofs = ((rr & 1) << 3) + l7;
    const int b_nofs = ((rr & 2) << 2);

    const int wo = warp >> 1;
    const int wn = warp & 1;

    float acc[8][4];
#pragma unroll
    for (int t = 0; t < 8; ++t)
#pragma unroll
        for (int e = 0; e < 4; ++e) acc[t][e] = 0.f;

    issueX(0, 0);
    cp_commit();

    for (int kc = 0; kc < 4; ++kc) {
        const int buf = kc & 1;
#pragma unroll
        for (int r = 0; r < 16; ++r) {
            int idx = tid + r * 256;
            int o = idx >> 6, cc = idx & 63;
            Wh[cc * WLD + o] = Wh_g[(size_t)(o0 + o) * CDIM + kc * 64 + cc];
            Wl[cc * WLD + o] = Wl_g[(size_t)(o0 + o) * CDIM + kc * 64 + cc];
        }
        if (kc < 3) { issueX(kc + 1, buf ^ 1); cp_commit(); cp_wait<1>(); }
        else        { cp_wait<0>(); }
        __syncthreads();

        const uint32_t x_cur = x_b + buf * xstride;

#pragma unroll
        for (int k0 = 0; k0 < 64; k0 += 16) {
            uint32_t ah[4], al[4];
            uint32_t aoff = (uint32_t)((k0 + a_kofs) * WLD + wo * 16 + a_mofs) * 2;
            ldsm_x4_t(ah, wh_b + aoff);
            ldsm_x4_t(al, wl_b + aoff);
#pragma unroll
            for (int jj = 0; jj < 4; ++jj) {
                uint32_t bx[4];
                uint32_t boff =
                    (uint32_t)((k0 + b_kofs) * XLD + wn * 64 + jj * 16 + b_nofs) * 2;
                ldsm_x4_t(bx, x_cur + boff);
                mma_fp16(acc[jj * 2 + 0], ah, bx + 0);
                mma_fp16(acc[jj * 2 + 1], ah, bx + 2);
                mma_fp16(acc[jj * 2 + 0], al, bx + 0);
                mma_fp16(acc[jj * 2 + 1], al, bx + 2);
            }
        }
        __syncthreads();
    }

    const int orow = wo * 16 + (lane >> 2);
    const float b0 = bias[o0 + orow];
    const float b1 = bias[o0 + orow + 8];
#pragma unroll
    for (int t = 0; t < 8; ++t) {
        int col = n0 + wn * 64 + t * 8 + (lane & 3) * 2;
        float v00 = acc[t][0] + b0, v01 = acc[t][1] + b0;
        float v10 = acc[t][2] + b1, v11 = acc[t][3] + b1;
        size_t i0 = ((size_t)b * R + o0 + orow) * NN + col;
        size_t i1 = ((size_t)b * R + o0 + orow + 8) * NN + col;
        if (Yf) {
            *(float2*)&Yf[i0] = make_float2(v00, v01);
            *(float2*)&Yf[i1] = make_float2(v10, v11);
        } else {
            *(__half2*)&Yh[i0] = __floats2half2_rn(v00, v01);
            *(__half2*)&Yh[i1] = __floats2half2_rn(v10, v11);
        }
    }
}

// ---------------------------------------------------------------------------
// Fused attention, single fp16, MERGED single-barrier pipeline.
// Per CTA: (b, 128 j). i tiled by 64 (64 iters).
// Iter it: [cp.async Q(it+1), V(it)] ; S(it) ; O(it-1) ; P(it)->smem ; barrier.
// Q/P/V double-buffered; K persistent. Numerics identical to R13.
// smem (halves): Q[2] 0/4608 (64x72), K 9216 (64x136),
//                P[2] 17920/26624 (64x136), V[2] 35328/53760 (256x72)
// total 72192 halves = 144384 B.
// ---------------------------------------------------------------------------
#define QLDh 72
#define KLDh 136
#define PLDh 136
#define VLDh 72
#define O_QB(buf) ((buf) * 64 * QLDh)
#define O_KH      (2 * 64 * QLDh)
#define O_PB(buf) (O_KH + 64 * KLDh + (buf) * 64 * PLDh)
#define O_VB(buf) (O_KH + 64 * KLDh + 2 * 64 * PLDh + (buf) * 256 * VLDh)
#define SM_ATTN ((O_VB(0) + 2 * 256 * VLDh) * 2)

__global__ __launch_bounds__(512) void attn_fp16_kernel()
{
    extern __shared__ __half smh[];
    const uint32_t sb = cvta_s(smh);

    const int b    = blockIdx.y;
    const int j0g  = blockIdx.x * 128;
    const int tid  = threadIdx.x;
    const int warp = tid >> 5;
    const int lane = tid & 31;

    const __half* Qb = g_Qf + (size_t)b * CKD * NN;
    const __half* Kb = g_Kf + (size_t)b * CKD * NN;
    const __half* Vb = g_Vf + (size_t)b * CDIM * NN;

    const uint32_t k_b = sb + O_KH * 2;

    // --- cp.async issuers ---
    auto issueQ = [&](int it, int buf) {
        int i0 = it * 64;
        int row = tid >> 3, c = tid & 7;
        cp16(sb + (uint32_t)(O_QB(buf) + row * QLDh + c * 8) * 2,
             Qb + (size_t)row * NN + i0 + c * 8);
    };
    auto issueV = [&](int it, int buf) {
        int i0 = it * 64;
#pragma unroll
        for (int r = 0; r < 4; ++r) {
            int idx = tid + r * 512;
            int row = idx >> 3, c = idx & 7;
            cp16(sb + (uint32_t)(O_VB(buf) + row * VLDh + c * 8) * 2,
                 Vb + (size_t)row * NN + i0 + c * 8);
        }
    };

    // prologue: Q(0) async + K tile (regular loads)
    issueQ(0, 0);
    cp_commit();
#pragma unroll
    for (int r = 0; r < 2; ++r) {
        int idx = tid + r * 512;
        int row = idx >> 4, c16 = idx & 15;
        *(uint4*)&smh[O_KH + row * KLDh + c16 * 8] =
            *(const uint4*)(Kb + (size_t)row * NN + j0g + c16 * 8);
    }
    cp_wait<0>();
    __syncthreads();

    // ldmatrix lane components (validated R4)
    const int l7 = lane & 7, rr = lane >> 3;
    const int a_dofs = ((rr & 2) << 2) + l7;
    const int a_iofs = ((rr & 1) << 3);
    const int b_kofs = ((rr & 1) << 3) + l7;
    const int b_jofs = ((rr & 2) << 2);
    const int v_row  = (lane & 15);
    const int v_col  = ((lane >> 4) << 3);

    const int s_i0 = (warp >> 2) * 16;            // S: 4 i-blocks of 16
    const int s_jb = (warp & 3) * 32;             // S: 4 j-groups of 32
    const int o_c0 = (warp >> 1) * 32;            // O: 8 c-groups of 32
    const int o_j0 = (warp & 1) * 64;             // O: 2 j-groups of 64

    float oacc[16][4];
#pragma unroll
    for (int t = 0; t < 16; ++t)
#pragma unroll
        for (int e = 0; e < 4; ++e) oacc[t][e] = 0.f;

    // O(prev) update from buffer vbuf
    auto o_step = [&](int vbuf) {
        const uint32_t vb = sb + (uint32_t)O_VB(vbuf) * 2;
        const uint32_t pb = sb + (uint32_t)O_PB(vbuf) * 2;
#pragma unroll
        for (int k0 = 0; k0 < 64; k0 += 16) {
            uint32_t vh0[4], vh1[4];
            uint32_t voff0 = (uint32_t)((o_c0 + v_row) * VLDh + k0 + v_col) * 2;
            uint32_t voff1 = (uint32_t)((o_c0 + 16 + v_row) * VLDh + k0 + v_col) * 2;
            ldsm_x4(vh0, vb + voff0);
            ldsm_x4(vh1, vb + voff1);
#pragma unroll
            for (int jj = 0; jj < 4; ++jj) {
                uint32_t ph[4];
                uint32_t poff =
                    (uint32_t)((k0 + b_kofs) * PLDh + o_j0 + jj * 16 + b_jofs) * 2;
                ldsm_x4_t(ph, pb + poff);
                mma_fp16(oacc[jj * 2 + 0], vh0, ph + 0);
                mma_fp16(oacc[jj * 2 + 1], vh0, ph + 2);
                mma_fp16(oacc[8 + jj * 2 + 0], vh1, ph + 0);
                mma_fp16(oacc[8 + jj * 2 + 1], vh1, ph + 2);
            }
        }
    };

    for (int it = 0; it < 64; ++it) {
        const int buf = it & 1;

        // async loads: Q(it+1) and V(it), both consumed next interval
        if (it < 63) issueQ(it + 1, buf ^ 1);
        issueV(it, buf);
        cp_commit();

        // ---- S(it) = Q^T K (warp: 16i x 32j), from Q[buf] ----
        float sacc[4][4];
#pragma unroll
        for (int t = 0; t < 4; ++t)
#pragma unroll
            for (int e = 0; e < 4; ++e) sacc[t][e] = 0.f;

        const uint32_t q_b = sb + (uint32_t)O_QB(buf) * 2;
#pragma unroll
        for (int k0 = 0; k0 < 64; k0 += 16) {
            uint32_t ah[4];
            uint32_t aoff = (uint32_t)((k0 + a_dofs) * QLDh + s_i0 + a_iofs) * 2;
            ldsm_x4_t(ah, q_b + aoff);
#pragma unroll
            for (int jj = 0; jj < 2; ++jj) {
                uint32_t bh[4];
                uint32_t boff =
                    (uint32_t)((k0 + b_kofs) * KLDh + s_jb + jj * 16 + b_jofs) * 2;
                ldsm_x4_t(bh, k_b + boff);
                mma_fp16(sacc[jj * 2 + 0], ah, bh + 0);
                mma_fp16(sacc[jj * 2 + 1], ah, bh + 2);
            }
        }

        // ---- O(it-1) += V(it-1) P(it-1), independent stream ----
        if (it > 0) o_step(buf ^ 1);

        // ---- P(it) = elu(S)/N -> P[buf] (S chains drained during O) ----
        {
            int prow = s_i0 + (lane >> 2);
            int pcol = (lane & 3) * 2;
            __half* Pb = smh + O_PB(buf);
#pragma unroll
            for (int t = 0; t < 4; ++t) {
                int jc = s_jb + t * 8 + pcol;
                __half p0 = __float2half(elu_scaled(sacc[t][0]));
                __half p1 = __float2half(elu_scaled(sacc[t][1]));
                __half p2 = __float2half(elu_scaled(sacc[t][2]));
                __half p3 = __float2half(elu_scaled(sacc[t][3]));
                *(__half2*)&Pb[prow * PLDh + jc] = __halves2half2(p0, p1);
                *(__half2*)&Pb[(prow + 8) * PLDh + jc] = __halves2half2(p2, p3);
            }
        }

        cp_wait<0>();        // Q(it+1), V(it) arrived
        __syncthreads();     // P(it) visible; Q[buf] free for it+1's prefetch
    }

    // final O(63) from buffer 1
    o_step(1);

    // ---- store O accumulators (single fp16) to scratch ----
#pragma unroll
    for (int cb = 0; cb < 2; ++cb) {
        int orow = o_c0 + cb * 16 + (lane >> 2);
#pragma unroll
        for (int jj = 0; jj < 4; ++jj) {
#pragma unroll
            for (int h = 0; h < 2; ++h) {
                float* a = oacc[cb * 8 + jj * 2 + h];
                int col = j0g + o_j0 + jj * 16 + h * 8 + (lane & 3) * 2;
                size_t i0 = ((size_t)b * CDIM + orow) * NN + col;
                size_t i1 = ((size_t)b * CDIM + orow + 8) * NN + col;
                *(__half2*)&g_Of[i0] = __floats2half2_rn(a[0], a[1]);
                *(__half2*)&g_Of[i1] = __floats2half2_rn(a[2], a[3]);
            }
        }
    }
}

// ---------------------------------------------------------------------------
extern "C" void kernel_launch(void* const* d_in, const int* in_sizes, int n_in,
                              void* d_out, int out_size)
{
    const float* x  = (const float*)d_in[0];
    const float* wq = (const float*)d_in[1];
    const float* bq = (const float*)d_in[2];
    const float* wk = (const float*)d_in[3];
    const float* bk = (const float*)d_in[4];
    const float* wv = (const float*)d_in[5];
    const float* bv = (const float*)d_in[6];
    const float* wg = (const float*)d_in[7];
    const float* bg = (const float*)d_in[8];
    float* out = (float*)d_out;

    __half *xf, *Qf, *Kf, *Vf, *Of;
    __half *Wqh, *Wql, *Wkh, *Wkl, *Wvh, *Wvl, *Wgh, *Wgl;
    cudaGetSymbolAddress((void**)&xf, g_xf);
    cudaGetSymbolAddress((void**)&Qf, g_Qf);
    cudaGetSymbolAddress((void**)&Kf, g_Kf);
    cudaGetSymbolAddress((void**)&Vf, g_Vf);
    cudaGetSymbolAddress((void**)&Of, g_Of);
    cudaGetSymbolAddress((void**)&Wqh, g_Wqh);
    cudaGetSymbolAddress((void**)&Wql, g_Wql);
    cudaGetSymbolAddress((void**)&Wkh, g_Wkh);
    cudaGetSymbolAddress((void**)&Wkl, g_Wkl);
    cudaGetSymbolAddress((void**)&Wvh, g_Wvh);
    cudaGetSymbolAddress((void**)&Wvl, g_Wvl);
    cudaGetSymbolAddress((void**)&Wgh, g_Wgh);
    cudaGetSymbolAddress((void**)&Wgl, g_Wgl);

    cudaFuncSetAttribute(attn_fp16_kernel, cudaFuncAttributeMaxDynamicSharedMemorySize,
                         SM_ATTN);
    const int smem_proj = (2 * 64 * WLD + 2 * 64 * XLD) * 2;
    cudaFuncSetAttribute(proj_fp16_kernel, cudaFuncAttributeMaxDynamicSharedMemorySize,
                         smem_proj);

    // 1. x -> fp16 single; weights -> fp16 hi/lo
    const int n4x = NB * CDIM * NN / 4;
    f2h_kernel<<<(n4x + 255) / 256, 256>>>(
        (const float4*)x, (__half2*)xf, n4x);
    const int n4s = CKD * CDIM / 4, n4b = CDIM * CDIM / 4;
    f2h_split_kernel<<<(n4s + 255) / 256, 256>>>(
        (const float4*)wq, (__half2*)Wqh, (__half2*)Wql, n4s);
    f2h_split_kernel<<<(n4s + 255) / 256, 256>>>(
        (const float4*)wk, (__half2*)Wkh, (__half2*)Wkl, n4s);
    f2h_split_kernel<<<(n4b + 255) / 256, 256>>>(
        (const float4*)wv, (__half2*)Wvh, (__half2*)Wvl, n4b);
    f2h_split_kernel<<<(n4b + 255) / 256, 256>>>(
        (const float4*)wg, (__half2*)Wgh, (__half2*)Wgl, n4b);

    // 2. QKV projections -> single fp16
    proj_fp16_kernel<<<dim3(NN / 128, CKD / 64, NB), 256, smem_proj>>>(
        Wqh, Wql, bq, xf, Qf, nullptr, CKD);
    proj_fp16_kernel<<<dim3(NN / 128, CKD / 64, NB), 256, smem_proj>>>(
        Wkh, Wkl, bk, xf, Kf, nullptr, CKD);
    proj_fp16_kernel<<<dim3(NN / 128, CDIM / 64, NB), 256, smem_proj>>>(
        Wvh, Wvl, bv, xf, Vf, nullptr, CDIM);

    // 3. Fused attention, merged single-barrier pipeline
    attn_fp16_kernel<<<dim3(NN / 128, NB), 512, SM_ATTN>>>();

    // 4. Final 1x1 conv (wg) -> fp32 output
    proj_fp16_kernel<<<dim3(NN / 128, CDIM / 64, NB), 256, smem_proj>>>(
        Wgh, Wgl, bg, Of, nullptr, out, CDIM);
}

// round 16
// speedup vs baseline: 1.0882x; 1.0882x over previous
#include <cuda_runtime.h>
#include <cuda_fp16.h>
#include <math.h>
#include <stdint.h>

#define NB   8
#define CDIM 256
#define CKD  64
#define NN   4096

// ---------------------------------------------------------------------------
// Scratch (allocation-free rule: __device__ globals). fp16 pipeline.
// ---------------------------------------------------------------------------
__device__ __half g_xf[NB * CDIM * NN];
__device__ __half g_Qf[NB * CKD  * NN];
__device__ __half g_Kf[NB * CKD  * NN];
__device__ __half g_Vf[NB * CDIM * NN];
__device__ __half g_Of[NB * CDIM * NN];
__device__ __half g_Wq[CKD * CDIM];
__device__ __half g_Wk[CKD * CDIM];
__device__ __half g_Wv[CDIM * CDIM];
__device__ __half g_Wg[CDIM * CDIM];

// ---------------------------------------------------------------------------
// Helpers (fragment maps validated R4-R6, fp16 MMA validated R12/R13)
// ---------------------------------------------------------------------------
__device__ __forceinline__ float elu_scaled(float x) {
    const float invN = 1.0f / 4096.0f;
    return (x > 0.f ? x : (expf(x) - 1.f)) * invN;
}
__device__ __forceinline__ uint32_t cvta_s(const void* p) {
    return (uint32_t)__cvta_generic_to_shared(p);
}
__device__ __forceinline__ void ldsm_x4(uint32_t* r, uint32_t addr) {
    asm volatile("ldmatrix.sync.aligned.m8n8.x4.shared.b16 {%0,%1,%2,%3},[%4];\n"
                 : "=r"(r[0]), "=r"(r[1]), "=r"(r[2]), "=r"(r[3]) : "r"(addr));
}
__device__ __forceinline__ void ldsm_x4_t(uint32_t* r, uint32_t addr) {
    asm volatile("ldmatrix.sync.aligned.m8n8.x4.trans.shared.b16 {%0,%1,%2,%3},[%4];\n"
                 : "=r"(r[0]), "=r"(r[1]), "=r"(r[2]), "=r"(r[3]) : "r"(addr));
}
__device__ __forceinline__ void mma_fp16(float* c, const uint32_t* a, const uint32_t* b) {
    asm volatile(
        "mma.sync.aligned.m16n8k16.row.col.f32.f16.f16.f32 "
        "{%0,%1,%2,%3},{%4,%5,%6,%7},{%8,%9},{%0,%1,%2,%3};\n"
        : "+f"(c[0]), "+f"(c[1]), "+f"(c[2]), "+f"(c[3])
        : "r"(a[0]), "r"(a[1]), "r"(a[2]), "r"(a[3]), "r"(b[0]), "r"(b[1]));
}
__device__ __forceinline__ void cp16(uint32_t saddr, const void* g) {
    asm volatile("cp.async.cg.shared.global [%0],[%1],16;\n" :: "r"(saddr), "l"(g));
}
__device__ __forceinline__ void cp_commit() {
    asm volatile("cp.async.commit_group;\n" ::: "memory");
}
template <int N> __device__ __forceinline__ void cp_wait() {
    asm volatile("cp.async.wait_group %0;\n" :: "n"(N) : "memory");
}

// ---------------------------------------------------------------------------
// fp32 -> fp16 conversions. One kernel for x, one fused kernel for weights.
// ---------------------------------------------------------------------------
__global__ __launch_bounds__(256) void f2h_kernel(
    const float4* __restrict__ in, __half2* __restrict__ o, int n4)
{
    int i = blockIdx.x * blockDim.x + threadIdx.x;
    if (i >= n4) return;
    float4 v = in[i];
    o[i * 2]     = __floats2half2_rn(v.x, v.y);
    o[i * 2 + 1] = __floats2half2_rn(v.z, v.w);
}

// all four weight matrices in one launch:
// [0,4096) wq | [4096,8192) wk | [8192,24576) wv | [24576,40960) wg  (float4 idx)
__global__ __launch_bounds__(256) void f2h_weights_kernel(
    const float4* __restrict__ wq, const float4* __restrict__ wk,
    const float4* __restrict__ wv, const float4* __restrict__ wg)
{
    int i = blockIdx.x * blockDim.x + threadIdx.x;
    if (i >= 40960) return;
    const float4* in;
    __half2* o;
    int off;
    if (i < 4096)       { in = wq; o = (__half2*)g_Wq; off = i; }
    else if (i < 8192)  { in = wk; o = (__half2*)g_Wk; off = i - 4096; }
    else if (i < 24576) { in = wv; o = (__half2*)g_Wv; off = i - 8192; }
    else                { in = wg; o = (__half2*)g_Wg; off = i - 24576; }
    float4 v = in[off];
    o[off * 2]     = __floats2half2_rn(v.x, v.y);
    o[off * 2 + 1] = __floats2half2_rn(v.z, v.w);
}

// ---------------------------------------------------------------------------
// fp16 projection core (single-fp16 W): Y = W X + bias
// CTA: 64o x 128n, K=256 in 4 chunks of 64, X double-buffered cp.async.
// smem: Ws[64][72] + X[2][64][136] halves = 44032 B -> 2 CTA/SM.
// ---------------------------------------------------------------------------
#define WLD 72
#define XLD 136
#define SMEM_PROJ ((64 * WLD + 2 * 64 * XLD) * 2)

__device__ __forceinline__ void proj_body(
    const __half* __restrict__ Wg_, const float* __restrict__ bias,
    const __half* __restrict__ Xb,
    __half* __restrict__ Yh, float* __restrict__ Yf,
    int o0, int R, int b, int n0, __half* sp)
{
    __half* Ws   = sp;                      // [64][WLD]
    __half* Xbuf = Ws + 64 * WLD;           // [2][64*XLD]

    const int tid  = threadIdx.x;
    const int warp = tid >> 5;
    const int lane = tid & 31;

    const uint32_t w_b = cvta_s(Ws);
    const uint32_t x_b = cvta_s(Xbuf);
    const uint32_t xstride = 64u * XLD * 2;

    const int l7 = lane & 7, rr = lane >> 3;
    const int a_kofs = ((rr & 2) << 2) + l7;
    const int a_mofs = ((rr & 1) << 3);
    const int b_kofs = ((rr & 1) << 3) + l7;
    const int b_nofs = ((rr & 2) << 2);

    const int wo = warp >> 1;     // 4 o-groups of 16
    const int wn = warp & 1;      // 2 n-groups of 64

    float acc[8][4];
#pragma unroll
    for (int t = 0; t < 8; ++t)
#pragma unroll
        for (int e = 0; e < 4; ++e) acc[t][e] = 0.f;

    // issue X chunk kc into buffer buf
    auto issueX = [&](int kc, int buf) {
#pragma unroll
        for (int r = 0; r < 4; ++r) {
            int idx = tid + r * 256;
            int row = idx >> 4, c16 = idx & 15;
            uint32_t d = x_b + buf * xstride + (uint32_t)(row * XLD + c16 * 8) * 2;
            cp16(d, Xb + (size_t)(kc * 64 + row) * NN + n0 + c16 * 8);
        }
    };

    issueX(0, 0);
    cp_commit();

    for (int kc = 0; kc < 4; ++kc) {
        const int buf = kc & 1;
        // W chunk (64o x 64c) -> Ws[cc][o]
#pragma unroll
        for (int r = 0; r < 16; ++r) {
            int idx = tid + r * 256;
            int o = idx >> 6, cc = idx & 63;
            Ws[cc * WLD + o] = Wg_[(size_t)(o0 + o) * CDIM + kc * 64 + cc];
        }
        if (kc < 3) { issueX(kc + 1, buf ^ 1); cp_commit(); cp_wait<1>(); }
        else        { cp_wait<0>(); }
        __syncthreads();

        const uint32_t x_cur = x_b + buf * xstride;

#pragma unroll
        for (int k0 = 0; k0 < 64; k0 += 16) {
            uint32_t ah[4];
            uint32_t aoff = (uint32_t)((k0 + a_kofs) * WLD + wo * 16 + a_mofs) * 2;
            ldsm_x4_t(ah, w_b + aoff);
#pragma unroll
            for (int jj = 0; jj < 4; ++jj) {
                uint32_t bx[4];
                uint32_t boff =
                    (uint32_t)((k0 + b_kofs) * XLD + wn * 64 + jj * 16 + b_nofs) * 2;
                ldsm_x4_t(bx, x_cur + boff);
                mma_fp16(acc[jj * 2 + 0], ah, bx + 0);
                mma_fp16(acc[jj * 2 + 1], ah, bx + 2);
            }
        }
        __syncthreads();
    }

    const int orow = wo * 16 + (lane >> 2);
    const float b0 = bias[o0 + orow];
    const float b1 = bias[o0 + orow + 8];
#pragma unroll
    for (int t = 0; t < 8; ++t) {
        int col = n0 + wn * 64 + t * 8 + (lane & 3) * 2;
        float v00 = acc[t][0] + b0, v01 = acc[t][1] + b0;
        float v10 = acc[t][2] + b1, v11 = acc[t][3] + b1;
        size_t i0 = ((size_t)b * R + o0 + orow) * NN + col;
        size_t i1 = ((size_t)b * R + o0 + orow + 8) * NN + col;
        if (Yf) {
            *(float2*)&Yf[i0] = make_float2(v00, v01);
            *(float2*)&Yf[i1] = make_float2(v10, v11);
        } else {
            *(__half2*)&Yh[i0] = __floats2half2_rn(v00, v01);
            *(__half2*)&Yh[i1] = __floats2half2_rn(v10, v11);
        }
    }
}

// Fused QKV projection: grid (NN/128, 6, NB). y: 0=Q, 1=K, 2..5=V chunk.
__global__ __launch_bounds__(256) void qkv_proj_kernel(
    const float* __restrict__ bq, const float* __restrict__ bk,
    const float* __restrict__ bv)
{
    extern __shared__ __half sp[];
    const int b  = blockIdx.z;
    const int n0 = blockIdx.x * 128;
    const int y  = blockIdx.y;

    const __half* Xb = g_xf + (size_t)b * CDIM * NN;
    const __half* W;
    const float* bias;
    __half* Y;
    int R, o0;
    if (y == 0)      { W = g_Wq; bias = bq; Y = g_Qf; R = CKD;  o0 = 0; }
    else if (y == 1) { W = g_Wk; bias = bk; Y = g_Kf; R = CKD;  o0 = 0; }
    else             { W = g_Wv; bias = bv; Y = g_Vf; R = CDIM; o0 = (y - 2) * 64; }

    proj_body(W, bias, Xb, Y, nullptr, o0, R, b, n0, sp);
}

// Final wg projection: grid (NN/128, 4, NB) -> fp32 out.
__global__ __launch_bounds__(256) void wg_proj_kernel(
    const float* __restrict__ bg, float* __restrict__ out)
{
    extern __shared__ __half sp[];
    const int b  = blockIdx.z;
    const int n0 = blockIdx.x * 128;
    const int o0 = blockIdx.y * 64;
    const __half* Xb = g_Of + (size_t)b * CDIM * NN;
    proj_body(g_Wg, bg, Xb, nullptr, out, o0, CDIM, b, n0, sp);
}

// ---------------------------------------------------------------------------
// Fused attention, single fp16 (R13-validated, unchanged).
// Per CTA: (b, 128 j). i tiled by 64.
// smem (halves): Q 0 (64x72), K 4608 (64x136), P 13312 (64x136),
//                V 22016 (256x72). total 40448 halves = 80896 B.
// ---------------------------------------------------------------------------
#define QLDh 72
#define KLDh 136
#define PLDh 136
#define VLDh 72
#define O_QH 0
#define O_KH (64 * QLDh)
#define O_PH (O_KH + 64 * KLDh)
#define O_VH (O_PH + 64 * PLDh)
#define SM_ATTN ((O_VH + 256 * VLDh) * 2)

__global__ __launch_bounds__(512) void attn_fp16_kernel()
{
    extern __shared__ __half smh[];
    const uint32_t sb = cvta_s(smh);

    const int b    = blockIdx.y;
    const int j0g  = blockIdx.x * 128;
    const int tid  = threadIdx.x;
    const int warp = tid >> 5;
    const int lane = tid & 31;

    const __half* Qb = g_Qf + (size_t)b * CKD * NN;
    const __half* Kb = g_Kf + (size_t)b * CKD * NN;
    const __half* Vb = g_Vf + (size_t)b * CDIM * NN;

    const uint32_t q_b = sb + O_QH * 2;
    const uint32_t k_b = sb + O_KH * 2;
    const uint32_t p_b = sb + O_PH * 2;
    const uint32_t v_b = sb + O_VH * 2;

    auto issueQ = [&](int it) {
        int i0 = it * 64;
        int row = tid >> 3, c = tid & 7;
        cp16(q_b + (uint32_t)(row * QLDh + c * 8) * 2,
             Qb + (size_t)row * NN + i0 + c * 8);
    };
    auto issueV = [&](int it) {
        int i0 = it * 64;
#pragma unroll
        for (int r = 0; r < 4; ++r) {
            int idx = tid + r * 512;
            int row = idx >> 3, c = idx & 7;
            cp16(v_b + (uint32_t)(row * VLDh + c * 8) * 2,
                 Vb + (size_t)row * NN + i0 + c * 8);
        }
    };

    issueQ(0);
    cp_commit();
#pragma unroll
    for (int r = 0; r < 2; ++r) {
        int idx = tid + r * 512;
        int row = idx >> 4, c16 = idx & 15;
        *(uint4*)&smh[O_KH + row * KLDh + c16 * 8] =
            *(const uint4*)(Kb + (size_t)row * NN + j0g + c16 * 8);
    }
    cp_wait<0>();
    __syncthreads();

    const int l7 = lane & 7, rr = lane >> 3;
    const int a_dofs = ((rr & 2) << 2) + l7;
    const int a_iofs = ((rr & 1) << 3);
    const int b_kofs = ((rr & 1) << 3) + l7;
    const int b_jofs = ((rr & 2) << 2);
    const int v_row  = (lane & 15);
    const int v_col  = ((lane >> 4) << 3);

    const int s_i0 = (warp >> 2) * 16;
    const int s_jb = (warp & 3) * 32;
    const int o_c0 = (warp >> 1) * 32;
    const int o_j0 = (warp & 1) * 64;

    float oacc[16][4];
#pragma unroll
    for (int t = 0; t < 16; ++t)
#pragma unroll
        for (int e = 0; e < 4; ++e) oacc[t][e] = 0.f;

    for (int it = 0; it < 64; ++it) {
        issueV(it);
        cp_commit();

        // ---- S = Q^T K (warp: 16i x 32j) ----
        float sacc[4][4];
#pragma unroll
        for (int t = 0; t < 4; ++t)
#pragma unroll
            for (int e = 0; e < 4; ++e) sacc[t][e] = 0.f;

#pragma unroll
        for (int k0 = 0; k0 < 64; k0 += 16) {
            uint32_t ah[4];
            uint32_t aoff = (uint32_t)((k0 + a_dofs) * QLDh + s_i0 + a_iofs) * 2;
            ldsm_x4_t(ah, q_b + aoff);
#pragma unroll
            for (int jj = 0; jj < 2; ++jj) {
                uint32_t bh[4];
                uint32_t boff =
                    (uint32_t)((k0 + b_kofs) * KLDh + s_jb + jj * 16 + b_jofs) * 2;
                ldsm_x4_t(bh, k_b + boff);
                mma_fp16(sacc[jj * 2 + 0], ah, bh + 0);
                mma_fp16(sacc[jj * 2 + 1], ah, bh + 2);
            }
        }

        // ---- P = elu(S)/N -> fp16 smem ----
        {
            int prow = s_i0 + (lane >> 2);
            int pcol = (lane & 3) * 2;
#pragma unroll
            for (int t = 0; t < 4; ++t) {
                int jc = s_jb + t * 8 + pcol;
                __half p0 = __float2half(elu_scaled(sacc[t][0]));
                __half p1 = __float2half(elu_scaled(sacc[t][1]));
                __half p2 = __float2half(elu_scaled(sacc[t][2]));
                __half p3 = __float2half(elu_scaled(sacc[t][3]));
                *(__half2*)&smh[O_PH + prow * PLDh + jc] = __halves2half2(p0, p1);
                *(__half2*)&smh[O_PH + (prow + 8) * PLDh + jc] = __halves2half2(p2, p3);
            }
        }
        cp_wait<0>();
        __syncthreads();

        if (it < 63) { issueQ(it + 1); cp_commit(); }

        // ---- O += V P (warp: 32c x 64j) ----
#pragma unroll
        for (int k0 = 0; k0 < 64; k0 += 16) {
            uint32_t vh0[4], vh1[4];
            {
                uint32_t voff0 = (uint32_t)((o_c0 + v_row) * VLDh + k0 + v_col) * 2;
                uint32_t voff1 = (uint32_t)((o_c0 + 16 + v_row) * VLDh + k0 + v_col) * 2;
                ldsm_x4(vh0, v_b + voff0);
                ldsm_x4(vh1, v_b + voff1);
            }
#pragma unroll
            for (int jj = 0; jj < 4; ++jj) {
                uint32_t ph[4];
                uint32_t poff =
                    (uint32_t)((k0 + b_kofs) * PLDh + o_j0 + jj * 16 + b_jofs) * 2;
                ldsm_x4_t(ph, p_b + poff);
                mma_fp16(oacc[jj * 2 + 0], vh0, ph + 0);
                mma_fp16(oacc[jj * 2 + 1], vh0, ph + 2);
                mma_fp16(oacc[8 + jj * 2 + 0], vh1, ph + 0);
                mma_fp16(oacc[8 + jj * 2 + 1], vh1, ph + 2);
            }
        }
        cp_wait<0>();
        __syncthreads();
    }

    // ---- store O accumulators (single fp16) to scratch ----
#pragma unroll
    for (int cb = 0; cb < 2; ++cb) {
        int orow = o_c0 + cb * 16 + (lane >> 2);
#pragma unroll
        for (int jj = 0; jj < 4; ++jj) {
#pragma unroll
            for (int h = 0; h < 2; ++h) {
                float* a = oacc[cb * 8 + jj * 2 + h];
                int col = j0g + o_j0 + jj * 16 + h * 8 + (lane & 3) * 2;
                size_t i0 = ((size_t)b * CDIM + orow) * NN + col;
                size_t i1 = ((size_t)b * CDIM + orow + 8) * NN + col;
                *(__half2*)&g_Of[i0] = __floats2half2_rn(a[0], a[1]);
                *(__half2*)&g_Of[i1] = __floats2half2_rn(a[2], a[3]);
            }
        }
    }
}

// ---------------------------------------------------------------------------
extern "C" void kernel_launch(void* const* d_in, const int* in_sizes, int n_in,
                              void* d_out, int out_size)
{
    const float* x  = (const float*)d_in[0];
    const float* wq = (const float*)d_in[1];
    const float* bq = (const float*)d_in[2];
    const float* wk = (const float*)d_in[3];
    const float* bk = (const float*)d_in[4];
    const float* wv = (const float*)d_in[5];
    const float* bv = (const float*)d_in[6];
    const float* wg = (const float*)d_in[7];
    const float* bg = (const float*)d_in[8];
    float* out = (float*)d_out;

    __half* xf;
    cudaGetSymbolAddress((void**)&xf, g_xf);

    cudaFuncSetAttribute(attn_fp16_kernel, cudaFuncAttributeMaxDynamicSharedMemorySize,
                         SM_ATTN);
    cudaFuncSetAttribute(qkv_proj_kernel, cudaFuncAttributeMaxDynamicSharedMemorySize,
                         SMEM_PROJ);
    cudaFuncSetAttribute(wg_proj_kernel, cudaFuncAttributeMaxDynamicSharedMemorySize,
                         SMEM_PROJ);

    // 1. conversions: x -> fp16 single; all four weights in one launch
    const int n4x = NB * CDIM * NN / 4;
    f2h_kernel<<<(n4x + 255) / 256, 256>>>((const float4*)x, (__half2*)xf, n4x);
    f2h_weights_kernel<<<160, 256>>>(
        (const float4*)wq, (const float4*)wk, (const float4*)wv, (const float4*)wg);

    // 2. fused QKV projection (single-fp16 W)
    qkv_proj_kernel<<<dim3(NN / 128, 6, NB), 256, SMEM_PROJ>>>(bq, bk, bv);

    // 3. fused attention (energy never materialized)
    attn_fp16_kernel<<<dim3(NN / 128, NB), 512, SM_ATTN>>>();

    // 4. final wg projection -> fp32 output
    wg_proj_kernel<<<dim3(NN / 128, 4, NB), 256, SMEM_PROJ>>>(bg, out);
}

// round 17
// speedup vs baseline: 1.2590x; 1.1570x over previous
#include <cuda_runtime.h>
#include <cuda_fp16.h>
#include <math.h>
#include <stdint.h>

#define NB   8
#define CDIM 256
#define CKD  64
#define NN   4096

// ---------------------------------------------------------------------------
// Scratch (allocation-free rule: __device__ globals). fp16 pipeline.
// ---------------------------------------------------------------------------
__device__ __half g_xf[NB * CDIM * NN];
__device__ __half g_Qf[NB * CKD  * NN];
__device__ __half g_Kf[NB * CKD  * NN];
__device__ __half g_Vf[NB * CDIM * NN];
__device__ __half g_Of[NB * CDIM * NN];
__device__ __half g_Wq[CKD * CDIM];
__device__ __half g_Wk[CKD * CDIM];
__device__ __half g_Wv[CDIM * CDIM];
__device__ __half g_Wg[CDIM * CDIM];

// ---------------------------------------------------------------------------
// Helpers (fragment maps validated R4-R6, fp16 MMA validated R12/R13)
// ---------------------------------------------------------------------------
__device__ __forceinline__ float elu_scaled(float x) {
    const float invN = 1.0f / 4096.0f;
    return (x > 0.f ? x : (__expf(x) - 1.f)) * invN;
}
__device__ __forceinline__ uint32_t cvta_s(const void* p) {
    return (uint32_t)__cvta_generic_to_shared(p);
}
__device__ __forceinline__ void ldsm_x4(uint32_t* r, uint32_t addr) {
    asm volatile("ldmatrix.sync.aligned.m8n8.x4.shared.b16 {%0,%1,%2,%3},[%4];\n"
                 : "=r"(r[0]), "=r"(r[1]), "=r"(r[2]), "=r"(r[3]) : "r"(addr));
}
__device__ __forceinline__ void ldsm_x4_t(uint32_t* r, uint32_t addr) {
    asm volatile("ldmatrix.sync.aligned.m8n8.x4.trans.shared.b16 {%0,%1,%2,%3},[%4];\n"
                 : "=r"(r[0]), "=r"(r[1]), "=r"(r[2]), "=r"(r[3]) : "r"(addr));
}
__device__ __forceinline__ void mma_fp16(float* c, const uint32_t* a, const uint32_t* b) {
    asm volatile(
        "mma.sync.aligned.m16n8k16.row.col.f32.f16.f16.f32 "
        "{%0,%1,%2,%3},{%4,%5,%6,%7},{%8,%9},{%0,%1,%2,%3};\n"
        : "+f"(c[0]), "+f"(c[1]), "+f"(c[2]), "+f"(c[3])
        : "r"(a[0]), "r"(a[1]), "r"(a[2]), "r"(a[3]), "r"(b[0]), "r"(b[1]));
}
__device__ __forceinline__ void cp16(uint32_t saddr, const void* g) {
    asm volatile("cp.async.cg.shared.global [%0],[%1],16;\n" :: "r"(saddr), "l"(g));
}
__device__ __forceinline__ void cp_commit() {
    asm volatile("cp.async.commit_group;\n" ::: "memory");
}
template <int N> __device__ __forceinline__ void cp_wait() {
    asm volatile("cp.async.wait_group %0;\n" :: "n"(N) : "memory");
}

// ---------------------------------------------------------------------------
// fp32 -> fp16 conversions (R15-validated).
// ---------------------------------------------------------------------------
__global__ __launch_bounds__(256) void f2h_kernel(
    const float4* __restrict__ in, __half2* __restrict__ o, int n4)
{
    int i = blockIdx.x * blockDim.x + threadIdx.x;
    if (i >= n4) return;
    float4 v = in[i];
    o[i * 2]     = __floats2half2_rn(v.x, v.y);
    o[i * 2 + 1] = __floats2half2_rn(v.z, v.w);
}

__global__ __launch_bounds__(256) void f2h_weights_kernel(
    const float4* __restrict__ wq, const float4* __restrict__ wk,
    const float4* __restrict__ wv, const float4* __restrict__ wg)
{
    int i = blockIdx.x * blockDim.x + threadIdx.x;
    if (i >= 40960) return;
    const float4* in;
    __half2* o;
    int off;
    if (i < 4096)       { in = wq; o = (__half2*)g_Wq; off = i; }
    else if (i < 8192)  { in = wk; o = (__half2*)g_Wk; off = i - 4096; }
    else if (i < 24576) { in = wv; o = (__half2*)g_Wv; off = i - 8192; }
    else                { in = wg; o = (__half2*)g_Wg; off = i - 24576; }
    float4 v = in[off];
    o[off * 2]     = __floats2half2_rn(v.x, v.y);
    o[off * 2 + 1] = __floats2half2_rn(v.z, v.w);
}

// ---------------------------------------------------------------------------
// fp16 projection core (R15-validated): Y = W X + bias
// ---------------------------------------------------------------------------
#define WLD 72
#define XLD 136
#define SMEM_PROJ ((64 * WLD + 2 * 64 * XLD) * 2)

__device__ __forceinline__ void proj_body(
    const __half* __restrict__ Wg_, const float* __restrict__ bias,
    const __half* __restrict__ Xb,
    __half* __restrict__ Yh, float* __restrict__ Yf,
    int o0, int R, int b, int n0, __half* sp)
{
    __half* Ws   = sp;
    __half* Xbuf = Ws + 64 * WLD;

    const int tid  = threadIdx.x;
    const int warp = tid >> 5;
    const int lane = tid & 31;

    const uint32_t w_b = cvta_s(Ws);
    const uint32_t x_b = cvta_s(Xbuf);
    const uint32_t xstride = 64u * XLD * 2;

    const int l7 = lane & 7, rr = lane >> 3;
    const int a_kofs = ((rr & 2) << 2) + l7;
    const int a_mofs = ((rr & 1) << 3);
    const int b_kofs = ((rr & 1) << 3) + l7;
    const int b_nofs = ((rr & 2) << 2);

    const int wo = warp >> 1;
    const int wn = warp & 1;

    float acc[8][4];
#pragma unroll
    for (int t = 0; t < 8; ++t)
#pragma unroll
        for (int e = 0; e < 4; ++e) acc[t][e] = 0.f;

    auto issueX = [&](int kc, int buf) {
#pragma unroll
        for (int r = 0; r < 4; ++r) {
            int idx = tid + r * 256;
            int row = idx >> 4, c16 = idx & 15;
            uint32_t d = x_b + buf * xstride + (uint32_t)(row * XLD + c16 * 8) * 2;
            cp16(d, Xb + (size_t)(kc * 64 + row) * NN + n0 + c16 * 8);
        }
    };

    issueX(0, 0);
    cp_commit();

    for (int kc = 0; kc < 4; ++kc) {
        const int buf = kc & 1;
#pragma unroll
        for (int r = 0; r < 16; ++r) {
            int idx = tid + r * 256;
            int o = idx >> 6, cc = idx & 63;
            Ws[cc * WLD + o] = Wg_[(size_t)(o0 + o) * CDIM + kc * 64 + cc];
        }
        if (kc < 3) { issueX(kc + 1, buf ^ 1); cp_commit(); cp_wait<1>(); }
        else        { cp_wait<0>(); }
        __syncthreads();

        const uint32_t x_cur = x_b + buf * xstride;

#pragma unroll
        for (int k0 = 0; k0 < 64; k0 += 16) {
            uint32_t ah[4];
            uint32_t aoff = (uint32_t)((k0 + a_kofs) * WLD + wo * 16 + a_mofs) * 2;
            ldsm_x4_t(ah, w_b + aoff);
#pragma unroll
            for (int jj = 0; jj < 4; ++jj) {
                uint32_t bx[4];
                uint32_t boff =
                    (uint32_t)((k0 + b_kofs) * XLD + wn * 64 + jj * 16 + b_nofs) * 2;
                ldsm_x4_t(bx, x_cur + boff);
                mma_fp16(acc[jj * 2 + 0], ah, bx + 0);
                mma_fp16(acc[jj * 2 + 1], ah, bx + 2);
            }
        }
        __syncthreads();
    }

    const int orow = wo * 16 + (lane >> 2);
    const float b0 = bias[o0 + orow];
    const float b1 = bias[o0 + orow + 8];
#pragma unroll
    for (int t = 0; t < 8; ++t) {
        int col = n0 + wn * 64 + t * 8 + (lane & 3) * 2;
        float v00 = acc[t][0] + b0, v01 = acc[t][1] + b0;
        float v10 = acc[t][2] + b1, v11 = acc[t][3] + b1;
        size_t i0 = ((size_t)b * R + o0 + orow) * NN + col;
        size_t i1 = ((size_t)b * R + o0 + orow + 8) * NN + col;
        if (Yf) {
            *(float2*)&Yf[i0] = make_float2(v00, v01);
            *(float2*)&Yf[i1] = make_float2(v10, v11);
        } else {
            *(__half2*)&Yh[i0] = __floats2half2_rn(v00, v01);
            *(__half2*)&Yh[i1] = __floats2half2_rn(v10, v11);
        }
    }
}

__global__ __launch_bounds__(256) void qkv_proj_kernel(
    const float* __restrict__ bq, const float* __restrict__ bk,
    const float* __restrict__ bv)
{
    extern __shared__ __half sp[];
    const int b  = blockIdx.z;
    const int n0 = blockIdx.x * 128;
    const int y  = blockIdx.y;

    const __half* Xb = g_xf + (size_t)b * CDIM * NN;
    const __half* W;
    const float* bias;
    __half* Y;
    int R, o0;
    if (y == 0)      { W = g_Wq; bias = bq; Y = g_Qf; R = CKD;  o0 = 0; }
    else if (y == 1) { W = g_Wk; bias = bk; Y = g_Kf; R = CKD;  o0 = 0; }
    else             { W = g_Wv; bias = bv; Y = g_Vf; R = CDIM; o0 = (y - 2) * 64; }

    proj_body(W, bias, Xb, Y, nullptr, o0, R, b, n0, sp);
}

__global__ __launch_bounds__(256) void wg_proj_kernel(
    const float* __restrict__ bg, float* __restrict__ out)
{
    extern __shared__ __half sp[];
    const int b  = blockIdx.z;
    const int n0 = blockIdx.x * 128;
    const int o0 = blockIdx.y * 64;
    const __half* Xb = g_Of + (size_t)b * CDIM * NN;
    proj_body(g_Wg, bg, Xb, nullptr, out, o0, CDIM, b, n0, sp);
}

// ---------------------------------------------------------------------------
// Fused attention, single fp16, 2 CTAs/SM. Per CTA: (b, 64 j). i tiled by 64.
// 256 threads (8 warps). Same per-warp work as R15's 512-thr version.
// smem (halves, LD=72): Q 0 (64x72), K 4608 (64x72), P 9216 (64x72),
//                       V 13824 (256x72). total 32256 halves = 64512 B.
// ---------------------------------------------------------------------------
#define ALD 72
#define O_QH 0
#define O_KH (64 * ALD)
#define O_PH (2 * 64 * ALD)
#define O_VH (3 * 64 * ALD)
#define SM_ATTN ((3 * 64 * ALD + 256 * ALD) * 2)

__global__ __launch_bounds__(256, 2) void attn_fp16_kernel()
{
    extern __shared__ __half smh[];
    const uint32_t sb = cvta_s(smh);

    const int b    = blockIdx.y;
    const int j0g  = blockIdx.x * 64;
    const int tid  = threadIdx.x;
    const int warp = tid >> 5;
    const int lane = tid & 31;

    const __half* Qb = g_Qf + (size_t)b * CKD * NN;
    const __half* Kb = g_Kf + (size_t)b * CKD * NN;
    const __half* Vb = g_Vf + (size_t)b * CDIM * NN;

    const uint32_t q_b = sb + O_QH * 2;
    const uint32_t k_b = sb + O_KH * 2;
    const uint32_t p_b = sb + O_PH * 2;
    const uint32_t v_b = sb + O_VH * 2;

    // --- cp.async issuers (tiles are 64 halves wide = 8 cp16 per row) ---
    auto issueQ = [&](int it) {
        int i0 = it * 64;
#pragma unroll
        for (int r = 0; r < 2; ++r) {
            int idx = tid + r * 256;
            int row = idx >> 3, c = idx & 7;
            cp16(q_b + (uint32_t)(row * ALD + c * 8) * 2,
                 Qb + (size_t)row * NN + i0 + c * 8);
        }
    };
    auto issueV = [&](int it) {
        int i0 = it * 64;
#pragma unroll
        for (int r = 0; r < 8; ++r) {
            int idx = tid + r * 256;
            int row = idx >> 3, c = idx & 7;
            cp16(v_b + (uint32_t)(row * ALD + c * 8) * 2,
                 Vb + (size_t)row * NN + i0 + c * 8);
        }
    };

    // prologue: Q(0) async + K tile (regular loads, 64 d x 64 j)
    issueQ(0);
    cp_commit();
#pragma unroll
    for (int r = 0; r < 2; ++r) {
        int idx = tid + r * 256;
        int row = idx >> 3, c8 = idx & 7;
        *(uint4*)&smh[O_KH + row * ALD + c8 * 8] =
            *(const uint4*)(Kb + (size_t)row * NN + j0g + c8 * 8);
    }
    cp_wait<0>();
    __syncthreads();

    // ldmatrix lane components (validated R4)
    const int l7 = lane & 7, rr = lane >> 3;
    const int a_dofs = ((rr & 2) << 2) + l7;
    const int a_iofs = ((rr & 1) << 3);
    const int b_kofs = ((rr & 1) << 3) + l7;
    const int b_jofs = ((rr & 2) << 2);
    const int v_row  = (lane & 15);
    const int v_col  = ((lane >> 4) << 3);

    // warp mappings (8 warps)
    const int s_i0 = (warp >> 1) * 16;       // S: 4 i-blocks of 16
    const int s_jb = (warp & 1) * 32;        // S: 2 j-groups of 32
    const int o_c0 = warp * 32;              // O: 8 c-groups of 32, all 64 j

    float oacc[16][4];
#pragma unroll
    for (int t = 0; t < 16; ++t)
#pragma unroll
        for (int e = 0; e < 4; ++e) oacc[t][e] = 0.f;

    for (int it = 0; it < 64; ++it) {
        // V(it) overlaps the S-phase
        issueV(it);
        cp_commit();

        // ---- S = Q^T K (warp: 16i x 32j) ----
        float sacc[4][4];
#pragma unroll
        for (int t = 0; t < 4; ++t)
#pragma unroll
            for (int e = 0; e < 4; ++e) sacc[t][e] = 0.f;

#pragma unroll
        for (int k0 = 0; k0 < 64; k0 += 16) {
            uint32_t ah[4];
            uint32_t aoff = (uint32_t)((k0 + a_dofs) * ALD + s_i0 + a_iofs) * 2;
            ldsm_x4_t(ah, q_b + aoff);
#pragma unroll
            for (int jj = 0; jj < 2; ++jj) {
                uint32_t bh[4];
                uint32_t boff =
                    (uint32_t)((k0 + b_kofs) * ALD + s_jb + jj * 16 + b_jofs) * 2;
                ldsm_x4_t(bh, k_b + boff);
                mma_fp16(sacc[jj * 2 + 0], ah, bh + 0);
                mma_fp16(sacc[jj * 2 + 1], ah, bh + 2);
            }
        }

        // ---- P = elu(S)/N -> fp16 smem ----
        {
            int prow = s_i0 + (lane >> 2);
            int pcol = (lane & 3) * 2;
#pragma unroll
            for (int t = 0; t < 4; ++t) {
                int jc = s_jb + t * 8 + pcol;
                __half p0 = __float2half(elu_scaled(sacc[t][0]));
                __half p1 = __float2half(elu_scaled(sacc[t][1]));
                __half p2 = __float2half(elu_scaled(sacc[t][2]));
                __half p3 = __float2half(elu_scaled(sacc[t][3]));
                *(__half2*)&smh[O_PH + prow * ALD + jc] = __halves2half2(p0, p1);
                *(__half2*)&smh[O_PH + (prow + 8) * ALD + jc] = __halves2half2(p2, p3);
            }
        }
        cp_wait<0>();        // V(it) arrived
        __syncthreads();     // P visible, Q free

        // Q(it+1) overlaps the O-phase
        if (it < 63) { issueQ(it + 1); cp_commit(); }

        // ---- O += V P (warp: 32c x 64j) ----
#pragma unroll
        for (int k0 = 0; k0 < 64; k0 += 16) {
            uint32_t vh0[4], vh1[4];
            {
                uint32_t voff0 = (uint32_t)((o_c0 + v_row) * ALD + k0 + v_col) * 2;
                uint32_t voff1 = (uint32_t)((o_c0 + 16 + v_row) * ALD + k0 + v_col) * 2;
                ldsm_x4(vh0, v_b + voff0);
                ldsm_x4(vh1, v_b + voff1);
            }
#pragma unroll
            for (int jj = 0; jj < 4; ++jj) {
                uint32_t ph[4];
                uint32_t poff =
                    (uint32_t)((k0 + b_kofs) * ALD + jj * 16 + b_jofs) * 2;
                ldsm_x4_t(ph, p_b + poff);
                mma_fp16(oacc[jj * 2 + 0], vh0, ph + 0);
                mma_fp16(oacc[jj * 2 + 1], vh0, ph + 2);
                mma_fp16(oacc[8 + jj * 2 + 0], vh1, ph + 0);
                mma_fp16(oacc[8 + jj * 2 + 1], vh1, ph + 2);
            }
        }
        cp_wait<0>();        // Q(it+1) arrived
        __syncthreads();     // V/P free
    }

    // ---- store O accumulators (single fp16) to scratch ----
#pragma unroll
    for (int cb = 0; cb < 2; ++cb) {
        int orow = o_c0 + cb * 16 + (lane >> 2);
#pragma unroll
        for (int jj = 0; jj < 4; ++jj) {
#pragma unroll
            for (int h = 0; h < 2; ++h) {
                float* a = oacc[cb * 8 + jj * 2 + h];
                int col = j0g + jj * 16 + h * 8 + (lane & 3) * 2;
                size_t i0 = ((size_t)b * CDIM + orow) * NN + col;
                size_t i1 = ((size_t)b * CDIM + orow + 8) * NN + col;
                *(__half2*)&g_Of[i0] = __floats2half2_rn(a[0], a[1]);
                *(__half2*)&g_Of[i1] = __floats2half2_rn(a[2], a[3]);
            }
        }
    }
}

// ---------------------------------------------------------------------------
extern "C" void kernel_launch(void* const* d_in, const int* in_sizes, int n_in,
                              void* d_out, int out_size)
{
    const float* x  = (const float*)d_in[0];
    const float* wq = (const float*)d_in[1];
    const float* bq = (const float*)d_in[2];
    const float* wk = (const float*)d_in[3];
    const float* bk = (const float*)d_in[4];
    const float* wv = (const float*)d_in[5];
    const float* bv = (const float*)d_in[6];
    const float* wg = (const float*)d_in[7];
    const float* bg = (const float*)d_in[8];
    float* out = (float*)d_out;

    __half* xf;
    cudaGetSymbolAddress((void**)&xf, g_xf);

    cudaFuncSetAttribute(attn_fp16_kernel, cudaFuncAttributeMaxDynamicSharedMemorySize,
                         SM_ATTN);
    cudaFuncSetAttribute(qkv_proj_kernel, cudaFuncAttributeMaxDynamicSharedMemorySize,
                         SMEM_PROJ);
    cudaFuncSetAttribute(wg_proj_kernel, cudaFuncAttributeMaxDynamicSharedMemorySize,
                         SMEM_PROJ);

    // 1. conversions
    const int n4x = NB * CDIM * NN / 4;
    f2h_kernel<<<(n4x + 255) / 256, 256>>>((const float4*)x, (__half2*)xf, n4x);
    f2h_weights_kernel<<<160, 256>>>(
        (const float4*)wq, (const float4*)wk, (const float4*)wv, (const float4*)wg);

    // 2. fused QKV projection
    qkv_proj_kernel<<<dim3(NN / 128, 6, NB), 256, SMEM_PROJ>>>(bq, bk, bv);

    // 3. fused attention, 2 CTA/SM (energy never materialized)
    attn_fp16_kernel<<<dim3(NN / 64, NB), 256, SM_ATTN>>>();

    // 4. final wg projection -> fp32 output
    wg_proj_kernel<<<dim3(NN / 128, 4, NB), 256, SMEM_PROJ>>>(bg, out);
}